// round 11
// baseline (speedup 1.0000x reference)
#include <cuda_runtime.h>
#include <cuda_bf16.h>

#define NUM_GRAPHS 256
#define EDGE_DIM   128
#define GLOBAL_DIM 256
#define LN_EPS     1e-5f
#define BLOCKS     592          // 148 SMs x 4 CTAs — exactly one wave
#define THREADS    256

// Scratch (allocation-free rule: __device__ globals).
// g_sums/g_counts zeroed at load and re-zeroed by the tail each replay.
// g_bar is a MONOTONIC arrival counter: replay R's tickets are exactly
// [592R, 592R+592) because graph replays serialize, so no reset is needed.
__device__ float    g_sums[NUM_GRAPHS * EDGE_DIM];
__device__ float    g_counts[NUM_GRAPHS];
__device__ unsigned g_bar = 0;

__device__ __forceinline__ void l2_prefetch(const void* p) {
    asm volatile("prefetch.global.L2 [%0];" :: "l"(p));
}

// One kernel: segment-sum phase -> ticket barrier -> fuse tail (blocks 0..255).
__global__ void __launch_bounds__(THREADS, 4) fused_kernel(
    const float4* __restrict__ edge4,   // [n_edges, 32] float4
    const int*    __restrict__ batch,   // [n_edges] int32, sorted
    const float*  __restrict__ W,       // [EDGE_DIM, GLOBAL_DIM]
    const float*  __restrict__ b,       // [GLOBAL_DIM]
    const float*  __restrict__ ln_w,    // [GLOBAL_DIM]
    const float*  __restrict__ ln_b,    // [GLOBAL_DIM]
    float*        __restrict__ out,     // [NUM_GRAPHS, GLOBAL_DIM]
    int n_edges, int chunk)
{
    // ---- L2 prefetch of fuse-phase params (survives the __ldcs stream) ----
    if (blockIdx.x < 8) {
        int idx = blockIdx.x * THREADS + threadIdx.x;    // 0..2047
        if (idx < 1024) {
            l2_prefetch(W + idx * 32);                   // 1024 x 128B = 128 KB
        } else if (idx < 1032) {
            l2_prefetch(b    + (idx - 1024) * 32);
        } else if (idx < 1040) {
            l2_prefetch(ln_w + (idx - 1032) * 32);
        } else if (idx < 1048) {
            l2_prefetch(ln_b + (idx - 1040) * 32);
        }
    }

    // ================= phase 1: segment sum (at HBM ceiling) =================
    {
        int warp = (blockIdx.x * THREADS + threadIdx.x) >> 5;
        int lane = threadIdx.x & 31;
        long long e0 = (long long)warp * chunk;
        long long e1 = e0 + chunk;
        if (e1 > n_edges) e1 = n_edges;

        if (e0 < e1) {
            int seg_last = batch[e1 - 1];
            long long e = e0;
            while (e < e1) {
                int seg = batch[e];
                long long end;
                if (seg == seg_last) {
                    end = e1;                       // common: rest of chunk is one run
                } else {
                    long long lo = e, hi = e1 - 1;  // batch[lo]==seg, batch[hi]!=seg
                    while (hi - lo > 1) {
                        long long mid = (lo + hi) >> 1;
                        if (batch[mid] == seg) lo = mid; else hi = mid;
                    }
                    end = hi;
                }

                float4 a0 = make_float4(0.f, 0.f, 0.f, 0.f);
                float4 a1 = make_float4(0.f, 0.f, 0.f, 0.f);
                const float4* p = edge4 + e * 32 + lane;
                long long n = end - e;
                long long i = 0;
                #pragma unroll 1
                for (; i + 8 <= n; i += 8) {
                    float4 v0 = __ldcs(p + (i + 0) * 32);
                    float4 v1 = __ldcs(p + (i + 1) * 32);
                    float4 v2 = __ldcs(p + (i + 2) * 32);
                    float4 v3 = __ldcs(p + (i + 3) * 32);
                    float4 v4 = __ldcs(p + (i + 4) * 32);
                    float4 v5 = __ldcs(p + (i + 5) * 32);
                    float4 v6 = __ldcs(p + (i + 6) * 32);
                    float4 v7 = __ldcs(p + (i + 7) * 32);
                    a0.x += v0.x + v1.x + v2.x + v3.x;
                    a0.y += v0.y + v1.y + v2.y + v3.y;
                    a0.z += v0.z + v1.z + v2.z + v3.z;
                    a0.w += v0.w + v1.w + v2.w + v3.w;
                    a1.x += v4.x + v5.x + v6.x + v7.x;
                    a1.y += v4.y + v5.y + v6.y + v7.y;
                    a1.z += v4.z + v5.z + v6.z + v7.z;
                    a1.w += v4.w + v5.w + v6.w + v7.w;
                }
                for (; i < n; i++) {
                    float4 v = __ldcs(p + i * 32);
                    a0.x += v.x; a0.y += v.y; a0.z += v.z; a0.w += v.w;
                }
                a0.x += a1.x; a0.y += a1.y; a0.z += a1.z; a0.w += a1.w;

                float* dst = &g_sums[seg * EDGE_DIM + lane * 4];
                atomicAdd(dst + 0, a0.x);
                atomicAdd(dst + 1, a0.y);
                atomicAdd(dst + 2, a0.z);
                atomicAdd(dst + 3, a0.w);
                if (lane == 0) atomicAdd(&g_counts[seg], (float)n);

                e = end;
            }
        }
    }

    // ================= ticket barrier =======================================
    // Ensure this block's atomics are globally visible, then arrive.
    __threadfence();
    __syncthreads();

    __shared__ unsigned s_ticket;
    if (threadIdx.x == 0) s_ticket = atomicAdd(&g_bar, 1u);

    // Non-tail blocks are done: their arrival is all the tail needs.
    if (blockIdx.x >= NUM_GRAPHS) return;

    __syncthreads();
    if (threadIdx.x == 0) {
        unsigned target = (s_ticket / BLOCKS + 1u) * BLOCKS;  // end of this replay's range
        // Plain L2 read polling (no RMW serialization), with backoff.
        while (__ldcg((const unsigned*)&g_bar) < target) __nanosleep(64);
    }
    __syncthreads();
    __threadfence();   // acquire: order polled flag before g_sums reads

    // ================= phase 2: fuse tail (blocks 0..255, one graph each) ===
    __shared__ float u_s[EDGE_DIM];
    __shared__ float red[8];
    __shared__ float bc[2];

    int g = blockIdx.x;
    int t = threadIdx.x;

    if (t < EDGE_DIM) {
        float c = fmaxf(g_counts[g], 1.0f);   // L2-hot from atomics
        u_s[t] = g_sums[g * EDGE_DIM + t] / c;
    }
    __syncthreads();

    // reset scratch for the next replay (after all reads above)
    if (t < EDGE_DIM) g_sums[g * EDGE_DIM + t] = 0.0f;
    if (t == 0)       g_counts[g] = 0.0f;

    // matmul: column t, W is L2-hot; 4 accumulators for FMA ILP, full unroll for MLP
    float acc0 = b[t], acc1 = 0.f, acc2 = 0.f, acc3 = 0.f;
    #pragma unroll
    for (int k = 0; k < EDGE_DIM; k += 4) {
        acc0 = fmaf(u_s[k + 0], W[(k + 0) * GLOBAL_DIM + t], acc0);
        acc1 = fmaf(u_s[k + 1], W[(k + 1) * GLOBAL_DIM + t], acc1);
        acc2 = fmaf(u_s[k + 2], W[(k + 2) * GLOBAL_DIM + t], acc2);
        acc3 = fmaf(u_s[k + 3], W[(k + 3) * GLOBAL_DIM + t], acc3);
    }
    float a = (acc0 + acc1) + (acc2 + acc3);

    int wid = t >> 5, lane = t & 31;

    // pass 1: mean
    float sum = a;
    #pragma unroll
    for (int o = 16; o; o >>= 1) sum += __shfl_xor_sync(0xffffffffu, sum, o);
    if (lane == 0) red[wid] = sum;
    __syncthreads();
    if (t == 0) {
        float S = 0.f;
        #pragma unroll
        for (int w = 0; w < 8; w++) S += red[w];
        bc[0] = S / (float)GLOBAL_DIM;
    }
    __syncthreads();
    float mu = bc[0];

    // pass 2: variance
    float d  = a - mu;
    float sq = d * d;
    #pragma unroll
    for (int o = 16; o; o >>= 1) sq += __shfl_xor_sync(0xffffffffu, sq, o);
    if (lane == 0) red[wid] = sq;
    __syncthreads();
    if (t == 0) {
        float Q = 0.f;
        #pragma unroll
        for (int w = 0; w < 8; w++) Q += red[w];
        bc[1] = rsqrtf(Q / (float)GLOBAL_DIM + LN_EPS);
    }
    __syncthreads();
    float inv = bc[1];

    out[g * GLOBAL_DIM + t] = d * inv * ln_w[t] + ln_b[t];
}

extern "C" void kernel_launch(void* const* d_in, const int* in_sizes, int n_in,
                              void* d_out, int out_size) {
    const float* edge_attr = (const float*)d_in[0];
    const int*   batch     = (const int*)d_in[1];
    const float* W         = (const float*)d_in[2];
    const float* b         = (const float*)d_in[3];
    const float* ln_w      = (const float*)d_in[4];
    const float* ln_b      = (const float*)d_in[5];
    float*       out       = (float*)d_out;

    int n_edges = in_sizes[1];

    const int warps = BLOCKS * (THREADS / 32);   // 4736
    int chunk = (n_edges + warps - 1) / warps;
    if (chunk < 1) chunk = 1;

    fused_kernel<<<BLOCKS, THREADS>>>((const float4*)edge_attr, batch,
                                      W, b, ln_w, ln_b, out, n_edges, chunk);
}

// round 12
// speedup vs baseline: 1.0045x; 1.0045x over previous
#include <cuda_runtime.h>
#include <cuda_bf16.h>

#define NUM_GRAPHS 256
#define EDGE_DIM   128
#define GLOBAL_DIM 256
#define LN_EPS     1e-5f

// Scratch (allocation-free rule: __device__ globals).
// Zero at module load; fuse_kernel re-zeros after use so graph replays stay clean.
__device__ float g_sums[NUM_GRAPHS * EDGE_DIM];
__device__ float g_counts[NUM_GRAPHS];

__device__ __forceinline__ void l2_prefetch(const void* p) {
    asm volatile("prefetch.global.L2 [%0];" :: "l"(p));
}

// One warp per contiguous chunk of ~423 edges. Lane l owns float4 columns [4l, 4l+4).
// Per segment-run inside the chunk: run end found in O(log chunk) broadcast loads
// (zero extra loads for single-segment chunks), then an unrolled streaming loop.
// At 7.16 TB/s this is at the HBM streaming ceiling — loop untouched.
// Blocks 0-7 additionally prefetch the fuse kernel's params into L2 (128 KB;
// the __ldcs evict-first edge stream leaves them resident).
__global__ void __launch_bounds__(256) segsum_kernel(
    const float4* __restrict__ edge4,   // [n_edges, 32] float4
    const int* __restrict__ batch,      // [n_edges] int32, sorted
    const float* __restrict__ W,
    const float* __restrict__ b,
    const float* __restrict__ ln_w,
    const float* __restrict__ ln_b,
    int n_edges, int chunk)
{
    if (blockIdx.x < 8) {
        int idx = blockIdx.x * 256 + threadIdx.x;        // 0..2047
        if (idx < 1024) {
            l2_prefetch(W + idx * 32);                   // 1024 x 128B = 128 KB
        } else if (idx < 1032) {
            l2_prefetch(b    + (idx - 1024) * 32);
        } else if (idx < 1040) {
            l2_prefetch(ln_w + (idx - 1032) * 32);
        } else if (idx < 1048) {
            l2_prefetch(ln_b + (idx - 1040) * 32);
        }
    }

    int warp  = (blockIdx.x * blockDim.x + threadIdx.x) >> 5;
    int lane  = threadIdx.x & 31;
    long long e0 = (long long)warp * chunk;
    long long e1 = e0 + chunk;
    if (e1 > n_edges) e1 = n_edges;
    if (e0 >= e1) return;

    int seg_last = batch[e1 - 1];

    long long e = e0;
    while (e < e1) {
        int seg = batch[e];
        long long end;
        if (seg == seg_last) {
            end = e1;                       // common case: rest of chunk is one run
        } else {
            long long lo = e, hi = e1 - 1;  // batch[lo]==seg, batch[hi]!=seg
            while (hi - lo > 1) {
                long long mid = (lo + hi) >> 1;
                if (batch[mid] == seg) lo = mid; else hi = mid;
            }
            end = hi;
        }

        float4 a0 = make_float4(0.f, 0.f, 0.f, 0.f);
        float4 a1 = make_float4(0.f, 0.f, 0.f, 0.f);
        const float4* p = edge4 + e * 32 + lane;
        long long n = end - e;
        long long i = 0;
        #pragma unroll 1
        for (; i + 8 <= n; i += 8) {
            float4 v0 = __ldcs(p + (i + 0) * 32);
            float4 v1 = __ldcs(p + (i + 1) * 32);
            float4 v2 = __ldcs(p + (i + 2) * 32);
            float4 v3 = __ldcs(p + (i + 3) * 32);
            float4 v4 = __ldcs(p + (i + 4) * 32);
            float4 v5 = __ldcs(p + (i + 5) * 32);
            float4 v6 = __ldcs(p + (i + 6) * 32);
            float4 v7 = __ldcs(p + (i + 7) * 32);
            a0.x += v0.x + v1.x + v2.x + v3.x;
            a0.y += v0.y + v1.y + v2.y + v3.y;
            a0.z += v0.z + v1.z + v2.z + v3.z;
            a0.w += v0.w + v1.w + v2.w + v3.w;
            a1.x += v4.x + v5.x + v6.x + v7.x;
            a1.y += v4.y + v5.y + v6.y + v7.y;
            a1.z += v4.z + v5.z + v6.z + v7.z;
            a1.w += v4.w + v5.w + v6.w + v7.w;
        }
        for (; i < n; i++) {
            float4 v = __ldcs(p + i * 32);
            a0.x += v.x; a0.y += v.y; a0.z += v.z; a0.w += v.w;
        }
        a0.x += a1.x; a0.y += a1.y; a0.z += a1.z; a0.w += a1.w;

        float* dst = &g_sums[seg * EDGE_DIM + lane * 4];
        atomicAdd(dst + 0, a0.x);
        atomicAdd(dst + 1, a0.y);
        atomicAdd(dst + 2, a0.z);
        atomicAdd(dst + 3, a0.w);
        if (lane == 0) atomicAdd(&g_counts[seg], (float)n);

        e = end;
    }
}

// One block (512 threads) per graph. 8-way k-split with float4 W loads:
// thread (q = t>>6, c4 = t&63) accumulates k in [16q, 16q+16) for columns
// [4*c4, 4*c4+4) — 16 independent LDG.128s (L2-hot via prefetch) into 4
// accumulators. Partials combine through smem, then two-pass LayerNorm.
// Also resets the scratch globals for the next graph replay.
__global__ void __launch_bounds__(512, 2) fuse_kernel(
    const float* __restrict__ W,    // [EDGE_DIM, GLOBAL_DIM]
    const float* __restrict__ b,    // [GLOBAL_DIM]
    const float* __restrict__ ln_w, // [GLOBAL_DIM]
    const float* __restrict__ ln_b, // [GLOBAL_DIM]
    float* __restrict__ out)        // [NUM_GRAPHS, GLOBAL_DIM]
{
    __shared__ float u_s[EDGE_DIM];
    __shared__ float part_s[8 * GLOBAL_DIM];   // 8 KB: [q][col]
    __shared__ float red[16];
    __shared__ float bc[2];

    int g = blockIdx.x;
    int t = threadIdx.x;

    if (t < EDGE_DIM) {
        float c = fmaxf(g_counts[g], 1.0f);
        u_s[t] = g_sums[g * EDGE_DIM + t] / c;
    }
    __syncthreads();

    // reset scratch for the next replay (after all reads above)
    if (t < EDGE_DIM) g_sums[g * EDGE_DIM + t] = 0.0f;
    if (t == 0)       g_counts[g] = 0.0f;

    int c4 = t & 63;   // float4 column group: cols [4*c4, 4*c4+4)
    int q  = t >> 6;   // k-group: k in [16q, 16q+16)

    const float4* W4 = (const float4*)W;        // [EDGE_DIM][64]
    const float4* wp = W4 + (q * 16) * 64 + c4;
    const float*  uq = u_s + q * 16;

    float4 acc = make_float4(0.f, 0.f, 0.f, 0.f);
    #pragma unroll
    for (int k = 0; k < 16; k++) {
        float4 w = wp[k * 64];
        float  u = uq[k];
        acc.x = fmaf(u, w.x, acc.x);
        acc.y = fmaf(u, w.y, acc.y);
        acc.z = fmaf(u, w.z, acc.z);
        acc.w = fmaf(u, w.w, acc.w);
    }
    // part_s[q][4*c4 .. 4*c4+3] = acc  (float4 store, conflict-free)
    ((float4*)part_s)[q * 64 + c4] = acc;
    __syncthreads();

    int half = t >> 8;           // 0 or 1
    float a = 0.0f;
    if (half == 0) {
        float s = b[t];
        #pragma unroll
        for (int qq = 0; qq < 8; qq++)
            s += part_s[qq * GLOBAL_DIM + t];   // stride-256 across qq, conflict-free per warp
        a = s;
    }

    int wid = t >> 5, lane = t & 31;

    // pass 1: mean (upper half contributes zeros; divide by GLOBAL_DIM)
    float sum = a;
    #pragma unroll
    for (int o = 16; o; o >>= 1) sum += __shfl_xor_sync(0xffffffffu, sum, o);
    if (lane == 0) red[wid] = sum;
    __syncthreads();
    if (t == 0) {
        float S = 0.f;
        #pragma unroll
        for (int w = 0; w < 16; w++) S += red[w];
        bc[0] = S / (float)GLOBAL_DIM;
    }
    __syncthreads();
    float mu = bc[0];

    // pass 2: variance (guard upper half to contribute zero)
    float d  = a - mu;
    float sq = (half == 0) ? d * d : 0.0f;
    #pragma unroll
    for (int o = 16; o; o >>= 1) sq += __shfl_xor_sync(0xffffffffu, sq, o);
    if (lane == 0) red[wid] = sq;
    __syncthreads();
    if (t == 0) {
        float Q = 0.f;
        #pragma unroll
        for (int w = 0; w < 16; w++) Q += red[w];
        bc[1] = rsqrtf(Q / (float)GLOBAL_DIM + LN_EPS);
    }
    __syncthreads();
    float inv = bc[1];

    if (half == 0)
        out[g * GLOBAL_DIM + t] = d * inv * ln_w[t] + ln_b[t];
}

extern "C" void kernel_launch(void* const* d_in, const int* in_sizes, int n_in,
                              void* d_out, int out_size) {
    const float* edge_attr = (const float*)d_in[0];
    const int*   batch     = (const int*)d_in[1];
    const float* W         = (const float*)d_in[2];
    const float* b         = (const float*)d_in[3];
    const float* ln_w      = (const float*)d_in[4];
    const float* ln_b      = (const float*)d_in[5];
    float*       out       = (float*)d_out;

    int n_edges = in_sizes[1];

    // Single wave: 4 CTAs/SM resident at any plausible register count.
    const int blocks = 592;                  // 148 SMs x 4 CTAs
    const int warps  = blocks * (256 / 32);  // 4736
    int chunk = (n_edges + warps - 1) / warps;
    if (chunk < 1) chunk = 1;
    segsum_kernel<<<blocks, 256>>>((const float4*)edge_attr, batch,
                                   W, b, ln_w, ln_b, n_edges, chunk);

    fuse_kernel<<<NUM_GRAPHS, 512>>>(W, b, ln_w, ln_b, out);
}

// round 14
// speedup vs baseline: 1.0114x; 1.0068x over previous
#include <cuda_runtime.h>
#include <cuda_bf16.h>

#define NUM_GRAPHS 256
#define EDGE_DIM   128
#define GLOBAL_DIM 256
#define LN_EPS     1e-5f

// Scratch (allocation-free rule: __device__ globals).
// Zero at module load; fuse_kernel re-zeros after use so graph replays stay clean.
__device__ float g_sums[NUM_GRAPHS * EDGE_DIM];
__device__ float g_counts[NUM_GRAPHS];

__device__ __forceinline__ void l2_prefetch(const void* p) {
    asm volatile("prefetch.global.L2 [%0];" :: "l"(p));
}

// One warp per contiguous chunk of ~423 edges. Lane l owns float4 columns [4l, 4l+4).
// Per segment-run inside the chunk: run end found in O(log chunk) broadcast loads
// (zero extra loads for single-segment chunks), then an unrolled streaming loop.
// At ~7.1 TB/s this is at the HBM streaming ceiling — loop untouched (exact R7 form).
// PDL: trigger at entry so the fuse grid launches immediately and fills SMs as
// segsum CTAs retire; data correctness comes from fuse's GridDependencySynchronize.
__global__ void __launch_bounds__(256) segsum_kernel(
    const float4* __restrict__ edge4,   // [n_edges, 32] float4
    const int* __restrict__ batch,      // [n_edges] int32, sorted
    int n_edges, int chunk)
{
    if (threadIdx.x == 0) cudaTriggerProgrammaticLaunchCompletion();

    int warp  = (blockIdx.x * blockDim.x + threadIdx.x) >> 5;
    int lane  = threadIdx.x & 31;
    long long e0 = (long long)warp * chunk;
    long long e1 = e0 + chunk;
    if (e1 > n_edges) e1 = n_edges;
    if (e0 >= e1) return;

    int seg_last = batch[e1 - 1];

    long long e = e0;
    while (e < e1) {
        int seg = batch[e];
        long long end;
        if (seg == seg_last) {
            end = e1;                       // common case: rest of chunk is one run
        } else {
            long long lo = e, hi = e1 - 1;  // batch[lo]==seg, batch[hi]!=seg
            while (hi - lo > 1) {
                long long mid = (lo + hi) >> 1;
                if (batch[mid] == seg) lo = mid; else hi = mid;
            }
            end = hi;
        }

        float4 a0 = make_float4(0.f, 0.f, 0.f, 0.f);
        float4 a1 = make_float4(0.f, 0.f, 0.f, 0.f);
        const float4* p = edge4 + e * 32 + lane;
        long long n = end - e;
        long long i = 0;
        #pragma unroll 1
        for (; i + 8 <= n; i += 8) {
            float4 v0 = __ldcs(p + (i + 0) * 32);
            float4 v1 = __ldcs(p + (i + 1) * 32);
            float4 v2 = __ldcs(p + (i + 2) * 32);
            float4 v3 = __ldcs(p + (i + 3) * 32);
            float4 v4 = __ldcs(p + (i + 4) * 32);
            float4 v5 = __ldcs(p + (i + 5) * 32);
            float4 v6 = __ldcs(p + (i + 6) * 32);
            float4 v7 = __ldcs(p + (i + 7) * 32);
            a0.x += v0.x + v1.x + v2.x + v3.x;
            a0.y += v0.y + v1.y + v2.y + v3.y;
            a0.z += v0.z + v1.z + v2.z + v3.z;
            a0.w += v0.w + v1.w + v2.w + v3.w;
            a1.x += v4.x + v5.x + v6.x + v7.x;
            a1.y += v4.y + v5.y + v6.y + v7.y;
            a1.z += v4.z + v5.z + v6.z + v7.z;
            a1.w += v4.w + v5.w + v6.w + v7.w;
        }
        for (; i < n; i++) {
            float4 v = __ldcs(p + i * 32);
            a0.x += v.x; a0.y += v.y; a0.z += v.z; a0.w += v.w;
        }
        a0.x += a1.x; a0.y += a1.y; a0.z += a1.z; a0.w += a1.w;

        float* dst = &g_sums[seg * EDGE_DIM + lane * 4];
        atomicAdd(dst + 0, a0.x);
        atomicAdd(dst + 1, a0.y);
        atomicAdd(dst + 2, a0.z);
        atomicAdd(dst + 3, a0.w);
        if (lane == 0) atomicAdd(&g_counts[seg], (float)n);

        e = end;
    }
}

// One block (512 threads) per graph, launched with PDL. Preamble (before the
// grid-dependency sync, overlapped with segsum's tail): prefetch W/b/ln into L2.
// Post-sync: 8-way k-split matmul on L2-hot W, partials via smem, two-pass LN.
// Also resets the scratch globals for the next graph replay.
__global__ void __launch_bounds__(512, 2) fuse_kernel(
    const float* __restrict__ W,    // [EDGE_DIM, GLOBAL_DIM]
    const float* __restrict__ b,    // [GLOBAL_DIM]
    const float* __restrict__ ln_w, // [GLOBAL_DIM]
    const float* __restrict__ ln_b, // [GLOBAL_DIM]
    float* __restrict__ out)        // [NUM_GRAPHS, GLOBAL_DIM]
{
    __shared__ float u_s[EDGE_DIM];
    __shared__ float part_s[8 * GLOBAL_DIM];   // 8 KB: [q][col]
    __shared__ float red[16];
    __shared__ float bc[2];

    int g = blockIdx.x;
    int t = threadIdx.x;

    // ---- preamble: runs while segsum is still streaming ----
    {
        int idx = t;            // 0..511; cover 1024 x 128B lines of W in 2 steps
        l2_prefetch(W + idx * 64);          // even lines
        l2_prefetch(W + (512 + idx) * 64);  // odd half
        if (t < 8)       l2_prefetch(b    + t * 32);
        else if (t < 16) l2_prefetch(ln_w + (t - 8) * 32);
        else if (t < 24) l2_prefetch(ln_b + (t - 16) * 32);
    }

    // ---- wait for segsum grid: all its atomics are now visible ----
    cudaGridDependencySynchronize();

    if (t < EDGE_DIM) {
        float c = fmaxf(g_counts[g], 1.0f);   // L2-hot from atomics
        u_s[t] = g_sums[g * EDGE_DIM + t] / c;
    }
    __syncthreads();

    // reset scratch for the next replay (after all reads above)
    if (t < EDGE_DIM) g_sums[g * EDGE_DIM + t] = 0.0f;
    if (t == 0)       g_counts[g] = 0.0f;

    int c4 = t & 63;   // float4 column group: cols [4*c4, 4*c4+4)
    int q  = t >> 6;   // k-group: k in [16q, 16q+16)

    const float4* W4 = (const float4*)W;        // [EDGE_DIM][64]
    const float4* wp = W4 + (q * 16) * 64 + c4;
    const float*  uq = u_s + q * 16;

    float4 acc = make_float4(0.f, 0.f, 0.f, 0.f);
    #pragma unroll
    for (int k = 0; k < 16; k++) {
        float4 w = wp[k * 64];
        float  u = uq[k];
        acc.x = fmaf(u, w.x, acc.x);
        acc.y = fmaf(u, w.y, acc.y);
        acc.z = fmaf(u, w.z, acc.z);
        acc.w = fmaf(u, w.w, acc.w);
    }
    // part_s[q][4*c4 .. 4*c4+3] = acc  (float4 store, conflict-free)
    ((float4*)part_s)[q * 64 + c4] = acc;
    __syncthreads();

    int half = t >> 8;           // 0 or 1
    float a = 0.0f;
    if (half == 0) {
        float s = b[t];
        #pragma unroll
        for (int qq = 0; qq < 8; qq++)
            s += part_s[qq * GLOBAL_DIM + t];   // stride-256 across qq, conflict-free per warp
        a = s;
    }

    int wid = t >> 5, lane = t & 31;

    // pass 1: mean (upper half contributes zeros; divide by GLOBAL_DIM)
    float sum = a;
    #pragma unroll
    for (int o = 16; o; o >>= 1) sum += __shfl_xor_sync(0xffffffffu, sum, o);
    if (lane == 0) red[wid] = sum;
    __syncthreads();
    if (t == 0) {
        float S = 0.f;
        #pragma unroll
        for (int w = 0; w < 16; w++) S += red[w];
        bc[0] = S / (float)GLOBAL_DIM;
    }
    __syncthreads();
    float mu = bc[0];

    // pass 2: variance (guard upper half to contribute zero)
    float d  = a - mu;
    float sq = (half == 0) ? d * d : 0.0f;
    #pragma unroll
    for (int o = 16; o; o >>= 1) sq += __shfl_xor_sync(0xffffffffu, sq, o);
    if (lane == 0) red[wid] = sq;
    __syncthreads();
    if (t == 0) {
        float Q = 0.f;
        #pragma unroll
        for (int w = 0; w < 16; w++) Q += red[w];
        bc[1] = rsqrtf(Q / (float)GLOBAL_DIM + LN_EPS);
    }
    __syncthreads();
    float inv = bc[1];

    if (half == 0)
        out[g * GLOBAL_DIM + t] = d * inv * ln_w[t] + ln_b[t];
}

extern "C" void kernel_launch(void* const* d_in, const int* in_sizes, int n_in,
                              void* d_out, int out_size) {
    const float* edge_attr = (const float*)d_in[0];
    const int*   batch     = (const int*)d_in[1];
    const float* W         = (const float*)d_in[2];
    const float* b         = (const float*)d_in[3];
    const float* ln_w      = (const float*)d_in[4];
    const float* ln_b      = (const float*)d_in[5];
    float*       out       = (float*)d_out;

    int n_edges = in_sizes[1];

    // Single wave: 4 CTAs/SM resident at any plausible register count.
    const int blocks = 592;                  // 148 SMs x 4 CTAs
    const int warps  = blocks * (256 / 32);  // 4736
    int chunk = (n_edges + warps - 1) / warps;
    if (chunk < 1) chunk = 1;
    segsum_kernel<<<blocks, 256>>>((const float4*)edge_attr, batch, n_edges, chunk);

    // Fuse kernel with programmatic dependent launch: launches early, preamble
    // prefetches W, GridDependencySynchronize gates the g_sums reads.
    cudaLaunchConfig_t cfg = {};
    cfg.gridDim  = dim3(NUM_GRAPHS);
    cfg.blockDim = dim3(512);
    cudaLaunchAttribute attrs[1];
    attrs[0].id = cudaLaunchAttributeProgrammaticStreamSerialization;
    attrs[0].val.programmaticStreamSerializationAllowed = 1;
    cfg.attrs = attrs;
    cfg.numAttrs = 1;
    cudaLaunchKernelEx(&cfg, fuse_kernel, W, b, ln_w, ln_b, out);
}